// round 2
// baseline (speedup 1.0000x reference)
#include <cuda_runtime.h>
#include <cuda_bf16.h>

// ExpmLogm on symmetric 3x3 per-voxel matrices:
//   eigh(M) -> (S, U);  S_log = log(exp(S)) = S;  out = U diag(S) U^T = M.
// The whole op is the identity on x (up to fp32 roundoff in the reference's
// eigh round-trip, ~1e-6 rel). Fastest correct kernel = pure D2D copy,
// HBM-bound: ~302 MB total traffic.

__global__ void expmlogm_copy_kernel(const float4* __restrict__ in,
                                     float4* __restrict__ out,
                                     int n4) {
    int i = blockIdx.x * blockDim.x + threadIdx.x;
    if (i < n4) {
        out[i] = in[i];
    }
}

// Tail handler in case element count isn't divisible by 4 (it is here:
// 2*9*128^3 = 37,748,736 = 4 * 9,437,184 — but keep it robust).
__global__ void expmlogm_copy_tail(const float* __restrict__ in,
                                   float* __restrict__ out,
                                   int start, int n) {
    int i = start + blockIdx.x * blockDim.x + threadIdx.x;
    if (i < n) {
        out[i] = in[i];
    }
}

extern "C" void kernel_launch(void* const* d_in, const int* in_sizes, int n_in,
                              void* d_out, int out_size) {
    const float* x = (const float*)d_in[0];
    float* out = (float*)d_out;
    int n = in_sizes[0];

    int n4 = n / 4;
    if (n4 > 0) {
        int threads = 256;
        int blocks = (n4 + threads - 1) / threads;
        expmlogm_copy_kernel<<<blocks, threads>>>(
            (const float4*)x, (float4*)out, n4);
    }
    int tail_start = n4 * 4;
    int tail = n - tail_start;
    if (tail > 0) {
        expmlogm_copy_tail<<<1, 128>>>(x, out, tail_start, n);
    }
}

// round 3
// speedup vs baseline: 1.0059x; 1.0059x over previous
#include <cuda_runtime.h>
#include <cuda_bf16.h>

// ExpmLogm on symmetric 3x3 per-voxel matrices collapses to the identity:
//   eigh(M) -> (S,U); log(exp(S)) = S; U diag(S) U^T = M.
// Optimal kernel = streaming D2D copy (~302 MB HBM traffic).
//
// R2 tuning vs the 1-float4/thread version (DRAM=75%):
//  - ILP=4: each thread issues 4 independent LDG.128 front-to-back (MLP_p1=4)
//    before any store, keeping the L1tex queue deep per warp.
//  - __ldcs/__stcs streaming hints: evict-first, avoid thrashing the 126MB L2
//    with a zero-reuse 302MB stream.

#define VPT 4          // float4 per thread
#define TPB 256        // threads per block

__global__ __launch_bounds__(TPB) void expmlogm_copy_kernel(
    const float4* __restrict__ in, float4* __restrict__ out, int n4) {
    // Block handles a contiguous chunk of TPB*VPT float4s; accesses within
    // each of the VPT sub-slices remain fully coalesced.
    int base = blockIdx.x * (TPB * VPT) + threadIdx.x;

    float4 v[VPT];
    int idx[VPT];
    // Front-batched loads (independent, all issued before any store)
    #pragma unroll
    for (int k = 0; k < VPT; k++) {
        idx[k] = base + k * TPB;
        if (idx[k] < n4) v[k] = __ldcs(&in[idx[k]]);
    }
    #pragma unroll
    for (int k = 0; k < VPT; k++) {
        if (idx[k] < n4) __stcs(&out[idx[k]], v[k]);
    }
}

// Tail (unused for this shape: 2*9*128^3 divisible by 4; guarded host-side).
__global__ void expmlogm_copy_tail(const float* __restrict__ in,
                                   float* __restrict__ out,
                                   int start, int n) {
    int i = start + blockIdx.x * blockDim.x + threadIdx.x;
    if (i < n) out[i] = in[i];
}

extern "C" void kernel_launch(void* const* d_in, const int* in_sizes, int n_in,
                              void* d_out, int out_size) {
    const float* x = (const float*)d_in[0];
    float* out = (float*)d_out;
    int n = in_sizes[0];

    int n4 = n / 4;
    if (n4 > 0) {
        int per_block = TPB * VPT;
        int blocks = (n4 + per_block - 1) / per_block;
        expmlogm_copy_kernel<<<blocks, TPB>>>(
            (const float4*)x, (float4*)out, n4);
    }
    int tail_start = n4 * 4;
    if (n - tail_start > 0) {
        expmlogm_copy_tail<<<1, 128>>>(x, out, tail_start, n);
    }
}